// round 16
// baseline (speedup 1.0000x reference)
#include <cuda_runtime.h>
#include <cuda_bf16.h>
#include <cstdint>

// ============================================================================
// Edge-MLP via algebraic split:
//   concat(f_s,f_d) @ W1^T == f_s @ W1a^T + f_d @ W1b^T
// Pass 1: persistent node GEMM, double-buffered A + stage, ONE barrier/tile.
// Pass 2: direct-LDG edge kernel, 64 edges/warp rolled batches, occ-pinned.
// ============================================================================

#define MAX_NODES 100000
#define HDIM 128
#define NSM 148
#define TROWS 64

__device__ __nv_bfloat16 g_P[(size_t)MAX_NODES * HDIM];   // P + b1 (bf16)
__device__ __nv_bfloat16 g_Q[(size_t)MAX_NODES * HDIM];

// ---- pass-1 smem layout (double buffered) ----
#define SA      272u                        // bf16 row: 256 B + 16 pad
#define SSTG    528u                        // stage row: 512 B + 16 pad
#define A_BYTES (64u * SA)                  // 17408
#define STG_BYTES (64u * SSTG)              // 33792
#define OFF_W    0u                         // 256 x 128 bf16 Wcat (69632 B)
#define OFF_A0   (256u * SA)                // 69632
#define OFF_A1   (OFF_A0 + A_BYTES)         // 87040
#define OFF_B1   (OFF_A1 + A_BYTES)         // 104448: float[128]
#define OFF_STG0 (OFF_B1 + 512u)            // 104960
#define OFF_STG1 (OFF_STG0 + STG_BYTES)     // 138752
#define GEMM_SMEM (OFF_STG1 + STG_BYTES)    // 172544

// ---------------------------------------------------------------------------
__device__ __forceinline__ uint32_t smem_u32(const void* p) {
    uint32_t a;
    asm("{ .reg .u64 t; cvta.to.shared.u64 t, %1; cvt.u32.u64 %0, t; }" : "=r"(a) : "l"(p));
    return a;
}
__device__ __forceinline__ void ldsm_x4(uint32_t* r, uint32_t addr) {
    asm volatile("ldmatrix.sync.aligned.m8n8.x4.shared.b16 {%0,%1,%2,%3}, [%4];"
                 : "=r"(r[0]), "=r"(r[1]), "=r"(r[2]), "=r"(r[3]) : "r"(addr));
}
__device__ __forceinline__ void mma_bf16(float* c, const uint32_t* a,
                                         uint32_t b0, uint32_t b1) {
    asm volatile(
        "mma.sync.aligned.m16n8k16.row.col.f32.bf16.bf16.f32 "
        "{%0,%1,%2,%3}, {%4,%5,%6,%7}, {%8,%9}, {%0,%1,%2,%3};"
        : "+f"(c[0]), "+f"(c[1]), "+f"(c[2]), "+f"(c[3])
        : "r"(a[0]), "r"(a[1]), "r"(a[2]), "r"(a[3]), "r"(b0), "r"(b1));
}
__device__ __forceinline__ void ldg128_nc(uint4& v, const void* p) {
    asm("ld.global.nc.v4.u32 {%0,%1,%2,%3}, [%4];"
        : "=r"(v.x), "=r"(v.y), "=r"(v.z), "=r"(v.w) : "l"(p));
}
__device__ __forceinline__ void sts32(uint32_t addr, uint32_t v) {
    asm volatile("st.shared.u32 [%0], %1;" :: "r"(addr), "r"(v) : "memory");
}
__device__ __forceinline__ void sts64(uint32_t addr, uint32_t lo, uint32_t hi) {
    asm volatile("st.shared.v2.u32 [%0], {%1, %2};" :: "r"(addr), "r"(lo), "r"(hi) : "memory");
}

// ---------------------------------------------------------------------------
// Pass 1: persistent node GEMM. One barrier per tile; A & stage double-buffered.
// Tile 64 nodes x 256 outs, K=128; 16 warps m16n64.
// ---------------------------------------------------------------------------
__device__ __forceinline__ void prefetch_A(uint4* pf, const float* __restrict__ feats,
                                           int row0, int nNodes) {
    int tid = threadIdx.x;
#pragma unroll
    for (int k = 0; k < 4; k++) {
        int id = k * 512 + tid;
        int r = id >> 5, c = id & 31;
        int node = row0 + r; if (node >= nNodes) node = nNodes - 1;
        ldg128_nc(pf[k], (const char*)(feats + (size_t)node * HDIM) + c * 16);
    }
}

__device__ __forceinline__ void convert_sts_A(const uint4* pf, uint32_t abase) {
    int tid = threadIdx.x;
#pragma unroll
    for (int k = 0; k < 4; k++) {
        int id = k * 512 + tid;
        int r = id >> 5, c = id & 31;
        const float* v = (const float*)&pf[k];
        __nv_bfloat162 lo = __floats2bfloat162_rn(v[0], v[1]);
        __nv_bfloat162 hi = __floats2bfloat162_rn(v[2], v[3]);
        sts64(abase + (uint32_t)r * SA + (uint32_t)c * 8u,
              *(const uint32_t*)&lo, *(const uint32_t*)&hi);
    }
}

__global__ __launch_bounds__(512, 1) void node_gemm_kernel(
    const float* __restrict__ feats, const float* __restrict__ W1,
    const float* __restrict__ b1, int nNodes)
{
    extern __shared__ char sm[];
    uint32_t sb = smem_u32(sm);
    int tid = threadIdx.x, wid = tid >> 5, lid = tid & 31;
    int ntiles = (nNodes + TROWS - 1) / TROWS;
    const uint32_t aoff[2] = {OFF_A0, OFF_A1};
    const uint32_t soff[2] = {OFF_STG0, OFF_STG1};

    uint4 pf[4];
    int t0 = blockIdx.x;
    if (t0 < ntiles)
        prefetch_A(pf, feats, t0 * TROWS, nNodes);

    if (tid < 128) ((float*)(sm + OFF_B1))[tid] = b1[tid];

    // W1 -> Wcat bf16 smem, once
    for (int idx = tid; idx < 256 * 64; idx += 512) {
        int j = idx >> 6, c2 = idx & 63;
        const float* wrow = W1 + (size_t)(j & 127) * 256 + ((j >> 7) << 7);
        float2 v = *(const float2*)(wrow + c2 * 2);
        *(__nv_bfloat162*)(sm + OFF_W + (uint32_t)j * SA + (uint32_t)c2 * 4u) =
            __floats2bfloat162_rn(v.x, v.y);
    }

    int mw = wid & 3, nw = wid >> 2;
    int mbase = mw * 16, nbase = nw * 64;
    uint32_t a_rel =
        (uint32_t)((mbase + (lid & 15)) * SA + ((lid >> 4) * 8) * 2);
    uint32_t b_lane = sb + OFF_W +
        (uint32_t)((nbase + (lid & 7) + ((lid >> 4) << 3)) * SA +
                   (((lid >> 3) & 1) * 8) * 2);

    if (t0 < ntiles) convert_sts_A(pf, sb + OFF_A0);
    __syncthreads();
    if (t0 + NSM < ntiles)
        prefetch_A(pf, feats, (t0 + NSM) * TROWS, nNodes);

    int cur = 0;
    for (int t = t0; t < ntiles; t += NSM) {
        int row0 = t * TROWS;

        // ---- mma on A[cur] ----
        float acc[8][4];
#pragma unroll
        for (int nt = 0; nt < 8; nt++)
#pragma unroll
            for (int q = 0; q < 4; q++) acc[nt][q] = 0.f;

        uint32_t a_lane = sb + aoff[cur] + a_rel;
#pragma unroll
        for (int ks = 0; ks < 8; ks++) {
            uint32_t koff = (uint32_t)ks * 32u;
            uint32_t a[4], b[4][4];
            ldsm_x4(a, a_lane + koff);
#pragma unroll
            for (int u = 0; u < 4; u++)
                ldsm_x4(b[u], b_lane + koff + (uint32_t)u * (16u * SA));
#pragma unroll
            for (int nt = 0; nt < 8; nt++) {
                int bt = nt >> 1, hi = (nt & 1) << 1;
                mma_bf16(acc[nt], a, b[bt][hi], b[bt][hi + 1]);
            }
        }

        // ---- fill A[nxt] from prefetched regs; refill pf two tiles ahead ----
        if (t + NSM < ntiles) convert_sts_A(pf, sb + aoff[cur ^ 1]);
        if (t + 2 * NSM < ntiles)
            prefetch_A(pf, feats, (t + 2 * NSM) * TROWS, nNodes);

        // ---- epilogue -> stage[cur] ----
        const float* b1s = (const float*)(sm + OFF_B1);
        uint32_t stg = sb + soff[cur];
#pragma unroll
        for (int nt = 0; nt < 8; nt++) {
            int r = mbase + (lid >> 2);
            int c0 = nbase + nt * 8 + 2 * (lid & 3);
            int isP = (c0 < 128);
            int cc = c0 & 127;
            float bA = isP ? b1s[cc] : 0.f;
            float bB = isP ? b1s[cc + 1] : 0.f;
            const float* c = acc[nt];
            __nv_bfloat162 v0 = __floats2bfloat162_rn(c[0] + bA, c[1] + bB);
            __nv_bfloat162 v1 = __floats2bfloat162_rn(c[2] + bA, c[3] + bB);
            sts32(stg + (uint32_t)r * SSTG + (uint32_t)c0 * 2u, *(const uint32_t*)&v0);
            sts32(stg + (uint32_t)(r + 8) * SSTG + (uint32_t)c0 * 2u, *(const uint32_t*)&v1);
        }

        __syncthreads();   // the ONE barrier: A[nxt] + stage[cur] visible

        // ---- coalesced copy-out of stage[cur] ----
        const char* stgr = sm + soff[cur];
#pragma unroll
        for (int it = 0; it < 4; it++) {
            int id = it * 512 + tid;
            int r = id >> 5, c = id & 31;
            int node = row0 + r;
            if (node < nNodes) {
                uint4 v = *(const uint4*)(stgr + (uint32_t)r * SSTG + (uint32_t)c * 16u);
                __nv_bfloat16* dstb = (c < 16 ? g_P : g_Q) + (size_t)node * HDIM + (c & 15) * 8;
                *(uint4*)dstb = v;
            }
        }
        cur ^= 1;
    }
}

// ---------------------------------------------------------------------------
// Pass 2: direct-LDG edge kernel. 64 edges/warp, rolled batch loop,
// occupancy pinned to 4 blocks/SM.
// ---------------------------------------------------------------------------
#define EW_WARPS 8    // 256-thr blocks
#define NBATCH   8    // 8-edge batches per warp

__device__ __forceinline__ int load_idx8(const int* __restrict__ src,
                                         const int* __restrict__ dst,
                                         int e0, int E, int lid) {
    int l = lid & 15;
    int e = e0 + (l & 7); if (e >= E) e = E - 1;
    return (l < 8) ? __ldg(src + e) : __ldg(dst + e);
}

__global__ __launch_bounds__(256, 4) void edge_kernel(
    const int* __restrict__ src, const int* __restrict__ dst,
    const float* __restrict__ W2, const float* __restrict__ b2,
    float* __restrict__ out, int E)
{
    int tid = threadIdx.x, wid = tid >> 5, lid = tid & 31;
    int g = lid & 7, sub = lid >> 3;

    int base = (blockIdx.x * EW_WARPS + wid) * (8 * NBATCH);
    if (base >= E) return;

    float wlo[8], whi[8];
#pragma unroll
    for (int i = 0; i < 4; i++) {
        float2 a = *(const float2*)(W2 + g * 8 + 2 * i);
        float2 b = *(const float2*)(W2 + 64 + g * 8 + 2 * i);
        wlo[2 * i] = a.x; wlo[2 * i + 1] = a.y;
        whi[2 * i] = b.x; whi[2 * i + 1] = b.y;
    }
    float b2v = __ldg(b2);

    int idx = load_idx8(src, dst, base, E, lid);
    const __nv_bfloat162 zero2 = __floats2bfloat162_rn(0.f, 0.f);

#pragma unroll 1
    for (int bt = 0; bt < NBATCH; bt++) {
        int e0 = base + bt * 8;
        if (e0 >= E) break;

        uint4 pv[2][2], qv[2][2];
#pragma unroll
        for (int b = 0; b < 2; b++) {
            int sN = __shfl_sync(0xFFFFFFFF, idx, b * 4 + sub);
            int dN = __shfl_sync(0xFFFFFFFF, idx, 8 + b * 4 + sub);
            const char* pb = (const char*)(g_P + (size_t)sN * HDIM);
            const char* qb = (const char*)(g_Q + (size_t)dN * HDIM);
            ldg128_nc(pv[b][0], pb + g * 16);
            ldg128_nc(pv[b][1], pb + 128 + g * 16);
            ldg128_nc(qv[b][0], qb + g * 16);
            ldg128_nc(qv[b][1], qb + 128 + g * 16);
        }
        if (bt + 1 < NBATCH && e0 + 8 < E)
            idx = load_idx8(src, dst, e0 + 8, E, lid);

#pragma unroll
        for (int b = 0; b < 2; b++) {
            float acc = 0.f;
            const uint32_t* plo = (const uint32_t*)&pv[b][0];
            const uint32_t* qlo = (const uint32_t*)&qv[b][0];
            const uint32_t* phi = (const uint32_t*)&pv[b][1];
            const uint32_t* qhi = (const uint32_t*)&qv[b][1];
#pragma unroll
            for (int i = 0; i < 4; i++) {
                __nv_bfloat162 h = __hmax2(
                    __hadd2(*(const __nv_bfloat162*)&plo[i],
                            *(const __nv_bfloat162*)&qlo[i]), zero2);
                float2 hf = __bfloat1622float2(h);
                acc = fmaf(hf.x, wlo[2 * i], acc);
                acc = fmaf(hf.y, wlo[2 * i + 1], acc);
            }
#pragma unroll
            for (int i = 0; i < 4; i++) {
                __nv_bfloat162 h = __hmax2(
                    __hadd2(*(const __nv_bfloat162*)&phi[i],
                            *(const __nv_bfloat162*)&qhi[i]), zero2);
                float2 hf = __bfloat1622float2(h);
                acc = fmaf(hf.x, whi[2 * i], acc);
                acc = fmaf(hf.y, whi[2 * i + 1], acc);
            }
#pragma unroll
            for (int d = 1; d <= 4; d <<= 1)
                acc += __shfl_xor_sync(0xFFFFFFFF, acc, d);
            if (g == 0) {
                int e = e0 + b * 4 + sub;
                if (e < E)
                    out[e] = 1.f / (1.f + __expf(-(acc + b2v)));
            }
        }
    }
}

// ---------------------------------------------------------------------------
extern "C" void kernel_launch(void* const* d_in, const int* in_sizes, int n_in,
                              void* d_out, int out_size) {
    const int*   src   = (const int*)d_in[0];
    const int*   dst   = (const int*)d_in[1];
    const float* feats = (const float*)d_in[2];
    const float* W1    = (const float*)d_in[3];
    const float* b1    = (const float*)d_in[4];
    const float* W2    = (const float*)d_in[5];
    const float* b2    = (const float*)d_in[6];
    float* out = (float*)d_out;
    int E = in_sizes[0];
    int nNodes = in_sizes[2] / HDIM;

    cudaFuncSetAttribute(node_gemm_kernel,
                         cudaFuncAttributeMaxDynamicSharedMemorySize, GEMM_SMEM);
    node_gemm_kernel<<<NSM, 512, GEMM_SMEM>>>(feats, W1, b1, nNodes);

    int epb = EW_WARPS * 8 * NBATCH;   // edges per block
    edge_kernel<<<(E + epb - 1) / epb, EW_WARPS * 32>>>(src, dst, W2, b2, out, E);
}

// round 17
// speedup vs baseline: 1.0579x; 1.0579x over previous
#include <cuda_runtime.h>
#include <cuda_bf16.h>
#include <cstdint>

// ============================================================================
// Edge-MLP via algebraic split:
//   concat(f_s,f_d) @ W1^T == f_s @ W1a^T + f_d @ W1b^T
// Pass 1: persistent node GEMM, m64n16 warp tiles, W1 B-fragments held in
//         registers across tiles (loaded once), double-buffered A + stage.
// Pass 2: direct-LDG edge kernel (frozen R15).
// ============================================================================

#define MAX_NODES 100000
#define HDIM 128
#define NSM 148
#define TROWS 64

__device__ __nv_bfloat16 g_P[(size_t)MAX_NODES * HDIM];   // P + b1 (bf16)
__device__ __nv_bfloat16 g_Q[(size_t)MAX_NODES * HDIM];

// ---- pass-1 smem layout (double buffered) ----
#define SA      272u                        // bf16 row: 256 B + 16 pad
#define SSTG    528u                        // stage row: 512 B + 16 pad
#define A_BYTES (64u * SA)                  // 17408
#define STG_BYTES (64u * SSTG)              // 33792
#define OFF_W    0u                         // 256 x 128 bf16 Wcat (69632 B)
#define OFF_A0   (256u * SA)                // 69632
#define OFF_A1   (OFF_A0 + A_BYTES)         // 87040
#define OFF_B1   (OFF_A1 + A_BYTES)         // 104448: float[128]
#define OFF_STG0 (OFF_B1 + 512u)            // 104960
#define OFF_STG1 (OFF_STG0 + STG_BYTES)     // 138752
#define GEMM_SMEM (OFF_STG1 + STG_BYTES)    // 172544

// ---------------------------------------------------------------------------
__device__ __forceinline__ uint32_t smem_u32(const void* p) {
    uint32_t a;
    asm("{ .reg .u64 t; cvta.to.shared.u64 t, %1; cvt.u32.u64 %0, t; }" : "=r"(a) : "l"(p));
    return a;
}
__device__ __forceinline__ void ldsm_x4(uint32_t* r, uint32_t addr) {
    asm volatile("ldmatrix.sync.aligned.m8n8.x4.shared.b16 {%0,%1,%2,%3}, [%4];"
                 : "=r"(r[0]), "=r"(r[1]), "=r"(r[2]), "=r"(r[3]) : "r"(addr));
}
__device__ __forceinline__ void mma_bf16(float* c, const uint32_t* a,
                                         uint32_t b0, uint32_t b1) {
    asm volatile(
        "mma.sync.aligned.m16n8k16.row.col.f32.bf16.bf16.f32 "
        "{%0,%1,%2,%3}, {%4,%5,%6,%7}, {%8,%9}, {%0,%1,%2,%3};"
        : "+f"(c[0]), "+f"(c[1]), "+f"(c[2]), "+f"(c[3])
        : "r"(a[0]), "r"(a[1]), "r"(a[2]), "r"(a[3]), "r"(b0), "r"(b1));
}
__device__ __forceinline__ void ldg128_nc(uint4& v, const void* p) {
    asm("ld.global.nc.v4.u32 {%0,%1,%2,%3}, [%4];"
        : "=r"(v.x), "=r"(v.y), "=r"(v.z), "=r"(v.w) : "l"(p));
}
__device__ __forceinline__ void sts32(uint32_t addr, uint32_t v) {
    asm volatile("st.shared.u32 [%0], %1;" :: "r"(addr), "r"(v) : "memory");
}
__device__ __forceinline__ void sts64(uint32_t addr, uint32_t lo, uint32_t hi) {
    asm volatile("st.shared.v2.u32 [%0], {%1, %2};" :: "r"(addr), "r"(lo), "r"(hi) : "memory");
}

// ---------------------------------------------------------------------------
// Pass 1: persistent node GEMM. Warp tile m64 x n16, K=128.
// Warp nw (0..15) owns Wcat cols [nw*16, nw*16+16) — B frags in registers.
// ---------------------------------------------------------------------------
__device__ __forceinline__ void prefetch_A(uint4* pf, const float* __restrict__ feats,
                                           int row0, int nNodes) {
    int tid = threadIdx.x;
#pragma unroll
    for (int k = 0; k < 4; k++) {
        int id = k * 512 + tid;
        int r = id >> 5, c = id & 31;
        int node = row0 + r; if (node >= nNodes) node = nNodes - 1;
        ldg128_nc(pf[k], (const char*)(feats + (size_t)node * HDIM) + c * 16);
    }
}

__device__ __forceinline__ void convert_sts_A(const uint4* pf, uint32_t abase) {
    int tid = threadIdx.x;
#pragma unroll
    for (int k = 0; k < 4; k++) {
        int id = k * 512 + tid;
        int r = id >> 5, c = id & 31;
        const float* v = (const float*)&pf[k];
        __nv_bfloat162 lo = __floats2bfloat162_rn(v[0], v[1]);
        __nv_bfloat162 hi = __floats2bfloat162_rn(v[2], v[3]);
        sts64(abase + (uint32_t)r * SA + (uint32_t)c * 8u,
              *(const uint32_t*)&lo, *(const uint32_t*)&hi);
    }
}

__global__ __launch_bounds__(512, 1) void node_gemm_kernel(
    const float* __restrict__ feats, const float* __restrict__ W1,
    const float* __restrict__ b1, int nNodes)
{
    extern __shared__ char sm[];
    uint32_t sb = smem_u32(sm);
    int tid = threadIdx.x, wid = tid >> 5, lid = tid & 31;
    int ntiles = (nNodes + TROWS - 1) / TROWS;
    const uint32_t aoff[2] = {OFF_A0, OFF_A1};
    const uint32_t soff[2] = {OFF_STG0, OFF_STG1};

    uint4 pf[4];
    int t0 = blockIdx.x;
    if (t0 < ntiles)
        prefetch_A(pf, feats, t0 * TROWS, nNodes);

    if (tid < 128) ((float*)(sm + OFF_B1))[tid] = b1[tid];

    // W1 -> Wcat bf16 smem, once
    for (int idx = tid; idx < 256 * 64; idx += 512) {
        int j = idx >> 6, c2 = idx & 63;
        const float* wrow = W1 + (size_t)(j & 127) * 256 + ((j >> 7) << 7);
        float2 v = *(const float2*)(wrow + c2 * 2);
        *(__nv_bfloat162*)(sm + OFF_W + (uint32_t)j * SA + (uint32_t)c2 * 4u) =
            __floats2bfloat162_rn(v.x, v.y);
    }

    int nw = wid;                       // warp owns cols [nw*16, nw*16+16)
    int nbase = nw * 16;
    uint32_t a_rel =
        (uint32_t)((lid & 15) * SA + ((lid >> 4) * 8) * 2);   // rows 0-15 base
    uint32_t b_lane = sb + OFF_W +
        (uint32_t)((nbase + (lid & 7) + ((lid >> 4) << 3)) * SA +
                   (((lid >> 3) & 1) * 8) * 2);

    if (t0 < ntiles) convert_sts_A(pf, sb + OFF_A0);
    __syncthreads();                    // A0 + Wcat visible

    // ---- load ALL B fragments into registers (once) ----
    uint32_t breg[8][4];
#pragma unroll
    for (int ks = 0; ks < 8; ks++)
        ldsm_x4(breg[ks], b_lane + (uint32_t)ks * 32u);

    if (t0 + NSM < ntiles)
        prefetch_A(pf, feats, (t0 + NSM) * TROWS, nNodes);

    int cur = 0;
    for (int t = t0; t < ntiles; t += NSM) {
        int row0 = t * TROWS;

        // ---- mma on A[cur]: m64 x n16 x k128 ----
        float acc[4][2][4];             // [mt 16-row][nt 8-col][quad]
#pragma unroll
        for (int mt = 0; mt < 4; mt++)
#pragma unroll
            for (int nt = 0; nt < 2; nt++)
#pragma unroll
                for (int q = 0; q < 4; q++) acc[mt][nt][q] = 0.f;

        uint32_t a_lane = sb + aoff[cur] + a_rel;
#pragma unroll
        for (int ks = 0; ks < 8; ks++) {
            uint32_t koff = (uint32_t)ks * 32u;
            uint32_t a[4][4];
#pragma unroll
            for (int mt = 0; mt < 4; mt++)
                ldsm_x4(a[mt], a_lane + koff + (uint32_t)mt * (16u * SA));
#pragma unroll
            for (int mt = 0; mt < 4; mt++) {
                mma_bf16(acc[mt][0], a[mt], breg[ks][0], breg[ks][1]);
                mma_bf16(acc[mt][1], a[mt], breg[ks][2], breg[ks][3]);
            }
        }

        // ---- fill A[nxt]; refill pf two tiles ahead ----
        if (t + NSM < ntiles) convert_sts_A(pf, sb + aoff[cur ^ 1]);
        if (t + 2 * NSM < ntiles)
            prefetch_A(pf, feats, (t + 2 * NSM) * TROWS, nNodes);

        // ---- epilogue -> stage[cur] ----
        const float* b1s = (const float*)(sm + OFF_B1);
        uint32_t stg = sb + soff[cur];
#pragma unroll
        for (int mt = 0; mt < 4; mt++)
#pragma unroll
            for (int nt = 0; nt < 2; nt++) {
                int r = mt * 16 + (lid >> 2);
                int c0 = nbase + nt * 8 + 2 * (lid & 3);
                int isP = (c0 < 128);
                int cc = c0 & 127;
                float bA = isP ? b1s[cc] : 0.f;
                float bB = isP ? b1s[cc + 1] : 0.f;
                const float* c = acc[mt][nt];
                __nv_bfloat162 v0 = __floats2bfloat162_rn(c[0] + bA, c[1] + bB);
                __nv_bfloat162 v1 = __floats2bfloat162_rn(c[2] + bA, c[3] + bB);
                sts32(stg + (uint32_t)r * SSTG + (uint32_t)c0 * 2u, *(const uint32_t*)&v0);
                sts32(stg + (uint32_t)(r + 8) * SSTG + (uint32_t)c0 * 2u, *(const uint32_t*)&v1);
            }

        __syncthreads();   // one barrier: A[nxt] + stage[cur] visible

        // ---- coalesced copy-out of stage[cur] ----
        const char* stgr = sm + soff[cur];
#pragma unroll
        for (int it = 0; it < 4; it++) {
            int id = it * 512 + tid;
            int r = id >> 5, c = id & 31;
            int node = row0 + r;
            if (node < nNodes) {
                uint4 v = *(const uint4*)(stgr + (uint32_t)r * SSTG + (uint32_t)c * 16u);
                __nv_bfloat16* dstb = (c < 16 ? g_P : g_Q) + (size_t)node * HDIM + (c & 15) * 8;
                *(uint4*)dstb = v;
            }
        }
        cur ^= 1;
    }
}

// ---------------------------------------------------------------------------
// Pass 2: direct-LDG edge kernel (frozen R15).
// ---------------------------------------------------------------------------
#define EW_WARPS 8    // 256-thr blocks
#define NBATCH   8    // 8-edge batches per warp

__device__ __forceinline__ int load_idx8(const int* __restrict__ src,
                                         const int* __restrict__ dst,
                                         int e0, int E, int lid) {
    int l = lid & 15;
    int e = e0 + (l & 7); if (e >= E) e = E - 1;
    return (l < 8) ? __ldg(src + e) : __ldg(dst + e);
}

__global__ __launch_bounds__(256, 4) void edge_kernel(
    const int* __restrict__ src, const int* __restrict__ dst,
    const float* __restrict__ W2, const float* __restrict__ b2,
    float* __restrict__ out, int E)
{
    int tid = threadIdx.x, wid = tid >> 5, lid = tid & 31;
    int g = lid & 7, sub = lid >> 3;

    int base = (blockIdx.x * EW_WARPS + wid) * (8 * NBATCH);
    if (base >= E) return;

    float wlo[8], whi[8];
#pragma unroll
    for (int i = 0; i < 4; i++) {
        float2 a = *(const float2*)(W2 + g * 8 + 2 * i);
        float2 b = *(const float2*)(W2 + 64 + g * 8 + 2 * i);
        wlo[2 * i] = a.x; wlo[2 * i + 1] = a.y;
        whi[2 * i] = b.x; whi[2 * i + 1] = b.y;
    }
    float b2v = __ldg(b2);

    int idx = load_idx8(src, dst, base, E, lid);
    const __nv_bfloat162 zero2 = __floats2bfloat162_rn(0.f, 0.f);

#pragma unroll 1
    for (int bt = 0; bt < NBATCH; bt++) {
        int e0 = base + bt * 8;
        if (e0 >= E) break;

        uint4 pv[2][2], qv[2][2];
#pragma unroll
        for (int b = 0; b < 2; b++) {
            int sN = __shfl_sync(0xFFFFFFFF, idx, b * 4 + sub);
            int dN = __shfl_sync(0xFFFFFFFF, idx, 8 + b * 4 + sub);
            const char* pb = (const char*)(g_P + (size_t)sN * HDIM);
            const char* qb = (const char*)(g_Q + (size_t)dN * HDIM);
            ldg128_nc(pv[b][0], pb + g * 16);
            ldg128_nc(pv[b][1], pb + 128 + g * 16);
            ldg128_nc(qv[b][0], qb + g * 16);
            ldg128_nc(qv[b][1], qb + 128 + g * 16);
        }
        if (bt + 1 < NBATCH && e0 + 8 < E)
            idx = load_idx8(src, dst, e0 + 8, E, lid);

#pragma unroll
        for (int b = 0; b < 2; b++) {
            float acc = 0.f;
            const uint32_t* plo = (const uint32_t*)&pv[b][0];
            const uint32_t* qlo = (const uint32_t*)&qv[b][0];
            const uint32_t* phi = (const uint32_t*)&pv[b][1];
            const uint32_t* qhi = (const uint32_t*)&qv[b][1];
#pragma unroll
            for (int i = 0; i < 4; i++) {
                __nv_bfloat162 h = __hmax2(
                    __hadd2(*(const __nv_bfloat162*)&plo[i],
                            *(const __nv_bfloat162*)&qlo[i]), zero2);
                float2 hf = __bfloat1622float2(h);
                acc = fmaf(hf.x, wlo[2 * i], acc);
                acc = fmaf(hf.y, wlo[2 * i + 1], acc);
            }
#pragma unroll
            for (int i = 0; i < 4; i++) {
                __nv_bfloat162 h = __hmax2(
                    __hadd2(*(const __nv_bfloat162*)&phi[i],
                            *(const __nv_bfloat162*)&qhi[i]), zero2);
                float2 hf = __bfloat1622float2(h);
                acc = fmaf(hf.x, whi[2 * i], acc);
                acc = fmaf(hf.y, whi[2 * i + 1], acc);
            }
#pragma unroll
            for (int d = 1; d <= 4; d <<= 1)
                acc += __shfl_xor_sync(0xFFFFFFFF, acc, d);
            if (g == 0) {
                int e = e0 + b * 4 + sub;
                if (e < E)
                    out[e] = 1.f / (1.f + __expf(-(acc + b2v)));
            }
        }
    }
}

// ---------------------------------------------------------------------------
extern "C" void kernel_launch(void* const* d_in, const int* in_sizes, int n_in,
                              void* d_out, int out_size) {
    const int*   src   = (const int*)d_in[0];
    const int*   dst   = (const int*)d_in[1];
    const float* feats = (const float*)d_in[2];
    const float* W1    = (const float*)d_in[3];
    const float* b1    = (const float*)d_in[4];
    const float* W2    = (const float*)d_in[5];
    const float* b2    = (const float*)d_in[6];
    float* out = (float*)d_out;
    int E = in_sizes[0];
    int nNodes = in_sizes[2] / HDIM;

    cudaFuncSetAttribute(node_gemm_kernel,
                         cudaFuncAttributeMaxDynamicSharedMemorySize, GEMM_SMEM);
    node_gemm_kernel<<<NSM, 512, GEMM_SMEM>>>(feats, W1, b1, nNodes);

    int epb = EW_WARPS * 8 * NBATCH;   // edges per block
    edge_kernel<<<(E + epb - 1) / epb, EW_WARPS * 32>>>(src, dst, W2, b2, out, E);
}